// round 2
// baseline (speedup 1.0000x reference)
#include <cuda_runtime.h>

#define BATCH 2048
#define INF   512
#define OUTF  512
#define NAG   64

#define TM 32
#define TN 64
#define TK 32
#define K2 (TK / 2)

__device__ int g_bucket[BATCH];
__device__ int g_offsets[NAG + 1];

typedef unsigned long long u64;

__device__ __forceinline__ u64 pack2(float a, float b) {
    u64 r; asm("mov.b64 %0, {%1, %2};" : "=l"(r) : "f"(a), "f"(b)); return r;
}
__device__ __forceinline__ void unpack2(u64 v, float& a, float& b) {
    asm("mov.b64 {%0, %1}, %2;" : "=f"(a), "=f"(b) : "l"(v));
}
__device__ __forceinline__ void ffma2(u64& d, u64 a, u64 b) {
    asm("fma.rn.f32x2 %0, %1, %2, %0;" : "+l"(d) : "l"(a), "l"(b));
}

// ---------------------------------------------------------------------------
// Kernel 1: counting sort of batch rows by agent id.
// ---------------------------------------------------------------------------
__global__ __launch_bounds__(1024) void bucket_kernel(const int* __restrict__ which) {
    __shared__ int cnt[NAG];
    __shared__ int run[NAG];
    const int t = threadIdx.x;
    if (t < NAG) cnt[t] = 0;
    __syncthreads();
    for (int i = t; i < BATCH; i += blockDim.x)
        atomicAdd(&cnt[which[i]], 1);
    __syncthreads();
    if (t == 0) {
        int s = 0;
        for (int a = 0; a < NAG; a++) { run[a] = s; g_offsets[a] = s; s += cnt[a]; }
        g_offsets[NAG] = s;
    }
    __syncthreads();
    for (int i = t; i < BATCH; i += blockDim.x) {
        const int a = which[i];
        const int p = atomicAdd(&run[a], 1);
        g_bucket[p] = i;
    }
}

// ---------------------------------------------------------------------------
// Kernel 2: per-(n-tile, agent, m-chunk) GEMM over gathered rows.
// grid = (OUTF/TN, NAG, 2). 128 threads; thread tile 4m x 4n; k packed in
// f32x2 pairs so BOTH operands come straight out of smem as u64 — inner loop
// is 4 LDS.128 + 16 FFMA2 per k-pair, no packing movs.
// acc u64 holds (even-k partial, odd-k partial); epilogue adds halves.
// ---------------------------------------------------------------------------
__global__ __launch_bounds__(128) void agent_gemm_kernel(
    const float* __restrict__ x, const float* __restrict__ w,
    const float* __restrict__ bias, float* __restrict__ out)
{
    const int a   = blockIdx.y;
    const int n0  = blockIdx.x * TN;
    const int off = g_offsets[a];
    const int cnt = g_offsets[a + 1] - off;

    __shared__ u64 Wp[K2][TN + 2];   // [k-pair][n]  (w2k, w2k+1)
    __shared__ u64 Xp[K2][TM + 2];   // [k-pair][m]  (x2k, x2k+1)

    const float* Wa = w + (size_t)a * OUTF * INF;
    const int t  = threadIdx.x;
    const int tn = t & 15;           // n-group: cols tn*4 .. +3
    const int tm = t >> 4;           // m-group: rows tm*4 .. +3
    // W load map: row wn = t>>1 (0..63), k-half wh = t&1 (16 floats = 64B)
    const int wn = t >> 1, wh = t & 1;
    // X load map: row xr = t>>2 (0..31), k-quarter xq = t&3 (8 floats = 32B)
    const int xr = t >> 2, xq = t & 3;

    // bias for this thread's 4 outputs
    float4 bv = *(const float4*)(bias + a * OUTF + n0 + tn * 4);

    for (int m0 = blockIdx.z * TM; m0 < cnt; m0 += 2 * TM) {
        const int xg = (m0 + xr < cnt) ? g_bucket[off + m0 + xr] : -1;
        const float* xrow = (xg >= 0) ? (x + (size_t)xg * INF + xq * 8) : nullptr;

        u64 acc[4][4];
        #pragma unroll
        for (int i = 0; i < 4; i++)
            #pragma unroll
            for (int j = 0; j < 4; j++) acc[i][j] = 0ull;

        for (int k0 = 0; k0 < INF; k0 += TK) {
            // ---- W tile: 64 rows x 32 k. 2 lanes/row -> coalesced 128B ----
            {
                const float4* src = (const float4*)(Wa + (size_t)(n0 + wn) * INF + k0 + wh * 16);
                #pragma unroll
                for (int j = 0; j < 4; j++) {
                    const float4 v = src[j];
                    const int kp = wh * 8 + j * 2;
                    Wp[kp][wn]     = pack2(v.x, v.y);
                    Wp[kp + 1][wn] = pack2(v.z, v.w);
                }
            }
            // ---- X tile: 32 rows x 32 k (gathered). 4 lanes/row ----
            if (xrow) {
                const float4* src = (const float4*)(xrow + k0);
                const float4 v0 = src[0], v1 = src[1];
                const int kp = xq * 4;
                Xp[kp][xr]     = pack2(v0.x, v0.y);
                Xp[kp + 1][xr] = pack2(v0.z, v0.w);
                Xp[kp + 2][xr] = pack2(v1.x, v1.y);
                Xp[kp + 3][xr] = pack2(v1.z, v1.w);
            } else {
                const int kp = xq * 4;
                Xp[kp][xr] = 0ull; Xp[kp+1][xr] = 0ull;
                Xp[kp+2][xr] = 0ull; Xp[kp+3][xr] = 0ull;
            }
            __syncthreads();

            #pragma unroll
            for (int kp = 0; kp < K2; kp++) {
                const ulonglong2* xp2 = (const ulonglong2*)&Xp[kp][tm * 4];
                const ulonglong2 xa = xp2[0], xb = xp2[1];
                const u64 xv[4] = {xa.x, xa.y, xb.x, xb.y};
                const ulonglong2* wp2 = (const ulonglong2*)&Wp[kp][tn * 4];
                const ulonglong2 wa = wp2[0], wb = wp2[1];
                const u64 wv[4] = {wa.x, wa.y, wb.x, wb.y};
                #pragma unroll
                for (int i = 0; i < 4; i++)
                    #pragma unroll
                    for (int j = 0; j < 4; j++)
                        ffma2(acc[i][j], xv[i], wv[j]);
            }
            __syncthreads();
        }

        // ---- epilogue: sum k-halves, add bias, scatter rows ----
        #pragma unroll
        for (int i = 0; i < 4; i++) {
            const int mA = m0 + tm * 4 + i;
            if (mA < cnt) {
                float lo0, hi0, lo1, hi1, lo2, hi2, lo3, hi3;
                unpack2(acc[i][0], lo0, hi0);
                unpack2(acc[i][1], lo1, hi1);
                unpack2(acc[i][2], lo2, hi2);
                unpack2(acc[i][3], lo3, hi3);
                const int r = g_bucket[off + mA];
                *(float4*)(out + (size_t)r * OUTF + n0 + tn * 4) =
                    make_float4(lo0 + hi0 + bv.x, lo1 + hi1 + bv.y,
                                lo2 + hi2 + bv.z, lo3 + hi3 + bv.w);
            }
        }
    }
}

extern "C" void kernel_launch(void* const* d_in, const int* in_sizes, int n_in,
                              void* d_out, int out_size) {
    const int*   which = (const int*)d_in[0];
    const float* x     = (const float*)d_in[1];
    const float* w     = (const float*)d_in[2];
    const float* b     = (const float*)d_in[3];
    float* out = (float*)d_out;

    bucket_kernel<<<1, 1024>>>(which);
    agent_gemm_kernel<<<dim3(OUTF / TN, NAG, 2), 128>>>(x, w, b, out);
}

// round 4
// speedup vs baseline: 1.3455x; 1.3455x over previous
#include <cuda_runtime.h>

#define BATCH 2048
#define INF   512
#define OUTF  512
#define NAG   64

#define TM 64
#define TN 64
#define TK 16
#define NCH (INF / TK)
#define WPAD 4   /* row stride 68 floats = 272B: 16B-aligned for LDS.128 */
#define XPAD 4

__device__ int g_bucket[BATCH];
__device__ int g_offsets[NAG + 1];

typedef unsigned long long u64;

__device__ __forceinline__ u64 pack2(float a, float b) {
    u64 r; asm("mov.b64 %0, {%1, %2};" : "=l"(r) : "f"(a), "f"(b)); return r;
}
__device__ __forceinline__ void unpack2(u64 v, float& a, float& b) {
    asm("mov.b64 {%0, %1}, %2;" : "=f"(a), "=f"(b) : "l"(v));
}
__device__ __forceinline__ void ffma2(u64& d, u64 a, u64 b) {
    asm("fma.rn.f32x2 %0, %1, %2, %0;" : "+l"(d) : "l"(a), "l"(b));
}

// ---------------------------------------------------------------------------
// Kernel 1: counting sort of batch rows by agent id.
// ---------------------------------------------------------------------------
__global__ __launch_bounds__(1024) void bucket_kernel(const int* __restrict__ which) {
    __shared__ int cnt[NAG];
    __shared__ int run[NAG];
    const int t = threadIdx.x;
    if (t < NAG) cnt[t] = 0;
    __syncthreads();
    for (int i = t; i < BATCH; i += blockDim.x)
        atomicAdd(&cnt[which[i]], 1);
    __syncthreads();
    if (t == 0) {
        int s = 0;
        for (int a = 0; a < NAG; a++) { run[a] = s; g_offsets[a] = s; s += cnt[a]; }
        g_offsets[NAG] = s;
    }
    __syncthreads();
    for (int i = t; i < BATCH; i += blockDim.x) {
        const int a = which[i];
        const int p = atomicAdd(&run[a], 1);
        g_bucket[p] = i;
    }
}

// ---------------------------------------------------------------------------
// Kernel 2: per-(n-tile, agent) GEMM over gathered rows, double-buffered.
// 64 threads (2 warps), thread tile 8m x 8n, m packed in f32x2 pairs.
// ---------------------------------------------------------------------------
__global__ __launch_bounds__(64) void agent_gemm_kernel(
    const float* __restrict__ x, const float* __restrict__ w,
    const float* __restrict__ bias, float* __restrict__ out)
{
    const int a   = blockIdx.y;
    const int n0  = blockIdx.x * TN;
    const int off = g_offsets[a];
    const int cnt = g_offsets[a + 1] - off;
    if (cnt == 0) return;

    __shared__ float Ws[2][TK][TN + WPAD];   // [stage][k][n]
    __shared__ float Xs[2][TK][TM + XPAD];   // [stage][k][m]

    const float* Wa = w + (size_t)a * OUTF * INF;
    const int t  = threadIdx.x;
    const int tn = t & 7;    // n-group: cols tn*8 .. +7
    const int tm = t >> 3;   // m-group: rows tm*8 .. +7
    const int wr = t >> 2;   // W load: row base 0..15 (x4 passes)
    const int wc = t & 3;    // W load: float4 col 0..3
    const int xr = t >> 1;   // X load: row 0..31 (+32 second pass)
    const int xh = t & 1;    // X load: k-half

    float bva[8];
    {
        const float4* bp = (const float4*)(bias + a * OUTF + n0 + tn * 8);
        const float4 b0 = bp[0], b1 = bp[1];
        bva[0]=b0.x; bva[1]=b0.y; bva[2]=b0.z; bva[3]=b0.w;
        bva[4]=b1.x; bva[5]=b1.y; bva[6]=b1.z; bva[7]=b1.w;
    }

    float4 wst[4], xst[4];

    auto ldg_chunk = [&](int c, const float* xA, const float* xB, int gA, int gB) {
        const int k0 = c * TK;
        #pragma unroll
        for (int p = 0; p < 4; p++)
            wst[p] = *(const float4*)(Wa + (size_t)(n0 + wr + 16 * p) * INF + k0 + wc * 4);
        if (gA >= 0) {
            xst[0] = *(const float4*)(xA + k0);
            xst[1] = *(const float4*)(xA + k0 + 4);
        } else {
            xst[0] = make_float4(0.f,0.f,0.f,0.f);
            xst[1] = make_float4(0.f,0.f,0.f,0.f);
        }
        if (gB >= 0) {
            xst[2] = *(const float4*)(xB + k0);
            xst[3] = *(const float4*)(xB + k0 + 4);
        } else {
            xst[2] = make_float4(0.f,0.f,0.f,0.f);
            xst[3] = make_float4(0.f,0.f,0.f,0.f);
        }
    };

    auto sts_stage = [&](int s) {
        #pragma unroll
        for (int p = 0; p < 4; p++) {
            const int n = wr + 16 * p;
            Ws[s][wc*4+0][n] = wst[p].x;
            Ws[s][wc*4+1][n] = wst[p].y;
            Ws[s][wc*4+2][n] = wst[p].z;
            Ws[s][wc*4+3][n] = wst[p].w;
        }
        const int kx = xh * 8;
        Xs[s][kx+0][xr] = xst[0].x; Xs[s][kx+1][xr] = xst[0].y;
        Xs[s][kx+2][xr] = xst[0].z; Xs[s][kx+3][xr] = xst[0].w;
        Xs[s][kx+4][xr] = xst[1].x; Xs[s][kx+5][xr] = xst[1].y;
        Xs[s][kx+6][xr] = xst[1].z; Xs[s][kx+7][xr] = xst[1].w;
        Xs[s][kx+0][xr+32] = xst[2].x; Xs[s][kx+1][xr+32] = xst[2].y;
        Xs[s][kx+2][xr+32] = xst[2].z; Xs[s][kx+3][xr+32] = xst[2].w;
        Xs[s][kx+4][xr+32] = xst[3].x; Xs[s][kx+5][xr+32] = xst[3].y;
        Xs[s][kx+6][xr+32] = xst[3].z; Xs[s][kx+7][xr+32] = xst[3].w;
    };

    for (int m0 = 0; m0 < cnt; m0 += TM) {
        const int gA = (m0 + xr      < cnt) ? g_bucket[off + m0 + xr]      : -1;
        const int gB = (m0 + xr + 32 < cnt) ? g_bucket[off + m0 + xr + 32] : -1;
        const float* xA = x + (size_t)(gA < 0 ? 0 : gA) * INF + xh * 8;
        const float* xB = x + (size_t)(gB < 0 ? 0 : gB) * INF + xh * 8;

        ldg_chunk(0, xA, xB, gA, gB);
        if (m0) __syncthreads();
        sts_stage(0);
        __syncthreads();

        u64 acc[4][8];
        #pragma unroll
        for (int i = 0; i < 4; i++)
            #pragma unroll
            for (int j = 0; j < 8; j++) acc[i][j] = 0ull;

        for (int c = 0; c < NCH; c++) {
            const int s = c & 1;
            if (c + 1 < NCH) ldg_chunk(c + 1, xA, xB, gA, gB);

            #pragma unroll
            for (int k = 0; k < TK; k++) {
                const ulonglong2* xp2 = (const ulonglong2*)&Xs[s][k][tm * 8];
                const ulonglong2 xa2 = xp2[0], xb2 = xp2[1];
                const u64 xp[4] = {xa2.x, xa2.y, xb2.x, xb2.y};
                const float4 w0 = *(const float4*)&Ws[s][k][tn * 8];
                const float4 w1 = *(const float4*)&Ws[s][k][tn * 8 + 4];
                const float wv[8] = {w0.x, w0.y, w0.z, w0.w,
                                     w1.x, w1.y, w1.z, w1.w};
                #pragma unroll
                for (int j = 0; j < 8; j++) {
                    const u64 wd = pack2(wv[j], wv[j]);
                    #pragma unroll
                    for (int i = 0; i < 4; i++) ffma2(acc[i][j], xp[i], wd);
                }
            }

            if (c + 1 < NCH) {
                sts_stage((c + 1) & 1);
                __syncthreads();
            }
        }

        // epilogue: unpack m-pairs, add bias, scatter rows
        #pragma unroll
        for (int i = 0; i < 4; i++) {
            float lo[8], hi[8];
            #pragma unroll
            for (int j = 0; j < 8; j++) unpack2(acc[i][j], lo[j], hi[j]);
            const int mA = m0 + tm * 8 + 2 * i;
            if (mA < cnt) {
                const int r = g_bucket[off + mA];
                float4* op = (float4*)(out + (size_t)r * OUTF + n0 + tn * 8);
                op[0] = make_float4(lo[0]+bva[0], lo[1]+bva[1], lo[2]+bva[2], lo[3]+bva[3]);
                op[1] = make_float4(lo[4]+bva[4], lo[5]+bva[5], lo[6]+bva[6], lo[7]+bva[7]);
            }
            if (mA + 1 < cnt) {
                const int r = g_bucket[off + mA + 1];
                float4* op = (float4*)(out + (size_t)r * OUTF + n0 + tn * 8);
                op[0] = make_float4(hi[0]+bva[0], hi[1]+bva[1], hi[2]+bva[2], hi[3]+bva[3]);
                op[1] = make_float4(hi[4]+bva[4], hi[5]+bva[5], hi[6]+bva[6], hi[7]+bva[7]);
            }
        }
    }
}

extern "C" void kernel_launch(void* const* d_in, const int* in_sizes, int n_in,
                              void* d_out, int out_size) {
    const int*   which = (const int*)d_in[0];
    const float* x     = (const float*)d_in[1];
    const float* w     = (const float*)d_in[2];
    const float* b     = (const float*)d_in[3];
    float* out = (float*)d_out;

    bucket_kernel<<<1, 1024>>>(which);
    agent_gemm_kernel<<<dim3(OUTF / TN, NAG), 64>>>(x, w, b, out);
}

// round 6
// speedup vs baseline: 1.7110x; 1.2717x over previous
#include <cuda_runtime.h>
#include <cuda_bf16.h>
#include <cstdint>

#define BATCH 2048
#define INF   512
#define OUTF  512
#define NAG   64

#define MT   128            /* block M (out features), 4 warps x 32 */
#define NT   32             /* block N (batch rows) */
#define TK   32             /* k chunk */
#define NCH  (INF / TK)     /* 16 */

/* smem: per stage: Whi[128x32 bf16, row stride 80B] + Wlo + Xhi[32x32] + Xlo */
#define WROW_B   80
#define ST_WHI   0
#define ST_WLO   10240
#define ST_XHI   20480
#define ST_XLO   23040
#define ST_SIZE  25600
#define SM_TOT   (2 * ST_SIZE)   /* 51200 bytes */

__device__ int g_bucket[BATCH];
__device__ int g_offsets[NAG + 1];

/* split 2 floats into packed bf16 hi-word and residual lo-word (lo 16 bits = f0) */
__device__ __forceinline__ void split2(float f0, float f1, uint32_t& h, uint32_t& l) {
    asm("cvt.rn.bf16x2.f32 %0, %1, %2;" : "=r"(h) : "f"(f1), "f"(f0));
    float r0 = f0 - __uint_as_float(h << 16);
    float r1 = f1 - __uint_as_float(h & 0xFFFF0000u);
    asm("cvt.rn.bf16x2.f32 %0, %1, %2;" : "=r"(l) : "f"(r1), "f"(r0));
}

__device__ __forceinline__ void mma_bf16(float* c, const uint32_t* a, const uint32_t* b) {
    asm volatile(
        "mma.sync.aligned.m16n8k16.row.col.f32.bf16.bf16.f32 "
        "{%0,%1,%2,%3}, {%4,%5,%6,%7}, {%8,%9}, {%0,%1,%2,%3};"
        : "+f"(c[0]), "+f"(c[1]), "+f"(c[2]), "+f"(c[3])
        : "r"(a[0]), "r"(a[1]), "r"(a[2]), "r"(a[3]), "r"(b[0]), "r"(b[1]));
}

/* ---------------- kernel 1: counting sort by agent ---------------- */
__global__ __launch_bounds__(1024) void bucket_kernel(const int* __restrict__ which) {
    __shared__ int cnt[NAG];
    __shared__ int run[NAG];
    const int t = threadIdx.x;
    if (t < NAG) cnt[t] = 0;
    __syncthreads();
    for (int i = t; i < BATCH; i += blockDim.x) atomicAdd(&cnt[which[i]], 1);
    __syncthreads();
    if (t == 0) {
        int s = 0;
        for (int a = 0; a < NAG; a++) { run[a] = s; g_offsets[a] = s; s += cnt[a]; }
        g_offsets[NAG] = s;
    }
    __syncthreads();
    for (int i = t; i < BATCH; i += blockDim.x) {
        const int a = which[i];
        g_bucket[atomicAdd(&run[a], 1)] = i;
    }
}

/* ---------------- kernel 2: split-bf16 mma.sync GEMM ----------------
   grid (OUTF/MT=4, NAG, 2). block 128 thr = 4 warps. Each warp: 32m x 32n.
   D = W_hi*X_hi + W_hi*X_lo + W_lo*X_hi  (fp32 accum), + bias.
*/
__global__ __launch_bounds__(128) void agent_mma_kernel(
    const float* __restrict__ x, const float* __restrict__ w,
    const float* __restrict__ bias, float* __restrict__ out)
{
    extern __shared__ char sm[];
    const int a     = blockIdx.y;
    const int mbase = blockIdx.x * MT;
    const int off   = g_offsets[a];
    const int cnt   = g_offsets[a + 1] - off;

    const int t    = threadIdx.x;
    const int lane = t & 31;
    const int warp = t >> 5;
    const int qr   = lane >> 2;   /* quad row 0..7 */
    const int qc   = lane & 3;    /* quad col 0..3 */

    const float* Wrow = w + (size_t)a * OUTF * INF + (size_t)(mbase + t) * INF;
    const int xrow = t & 31, xq = t >> 5;   /* X: row, k-octet */

    float4 wpre[8], xpre[2];

    for (int n0 = blockIdx.z * NT; n0 < cnt; n0 += 2 * NT) {
        const int cntc = min(NT, cnt - n0);
        const int xg = (xrow < cntc) ? g_bucket[off + n0 + xrow] : g_bucket[off];
        const float* xp = x + (size_t)xg * INF + xq * 8;

        float acc[2][4][4];
        #pragma unroll
        for (int mi = 0; mi < 2; mi++)
            #pragma unroll
            for (int ni = 0; ni < 4; ni++)
                #pragma unroll
                for (int r = 0; r < 4; r++) acc[mi][ni][r] = 0.f;

        auto ldg = [&](int c) {
            const int k0 = c * TK;
            #pragma unroll
            for (int p = 0; p < 8; p++)
                wpre[p] = *(const float4*)(Wrow + k0 + p * 4);
            xpre[0] = *(const float4*)(xp + k0);
            xpre[1] = *(const float4*)(xp + k0 + 4);
        };

        auto sts = [&](int s) {
            char* base = sm + s * ST_SIZE;
            uint32_t hw[16], lw[16];
            #pragma unroll
            for (int p = 0; p < 8; p++) {
                split2(wpre[p].x, wpre[p].y, hw[2 * p],     lw[2 * p]);
                split2(wpre[p].z, wpre[p].w, hw[2 * p + 1], lw[2 * p + 1]);
            }
            char* dw = base + (uint32_t)t * WROW_B;
            #pragma unroll
            for (int q = 0; q < 4; q++) {
                *(uint4*)(dw + ST_WHI + q * 16) =
                    make_uint4(hw[4*q], hw[4*q+1], hw[4*q+2], hw[4*q+3]);
                *(uint4*)(dw + ST_WLO + q * 16) =
                    make_uint4(lw[4*q], lw[4*q+1], lw[4*q+2], lw[4*q+3]);
            }
            uint32_t hx[4], lx[4];
            split2(xpre[0].x, xpre[0].y, hx[0], lx[0]);
            split2(xpre[0].z, xpre[0].w, hx[1], lx[1]);
            split2(xpre[1].x, xpre[1].y, hx[2], lx[2]);
            split2(xpre[1].z, xpre[1].w, hx[3], lx[3]);
            char* dx = base + (uint32_t)xrow * WROW_B + xq * 16;
            *(uint4*)(dx + ST_XHI) = make_uint4(hx[0], hx[1], hx[2], hx[3]);
            *(uint4*)(dx + ST_XLO) = make_uint4(lx[0], lx[1], lx[2], lx[3]);
        };

        auto compute = [&](int s) {
            const char* base = sm + s * ST_SIZE;
            #pragma unroll
            for (int kk = 0; kk < 2; kk++) {
                const int kb = (kk * 16 + qc * 2) * 2;   /* byte offset of k col */
                uint32_t ahi[2][4], alo[2][4];
                #pragma unroll
                for (int mi = 0; mi < 2; mi++) {
                    const int r0 = warp * 32 + mi * 16 + qr;
                    const char* ph = base + ST_WHI + r0 * WROW_B + kb;
                    const char* pl = base + ST_WLO + r0 * WROW_B + kb;
                    ahi[mi][0] = *(const uint32_t*)(ph);
                    ahi[mi][1] = *(const uint32_t*)(ph + 8 * WROW_B);
                    ahi[mi][2] = *(const uint32_t*)(ph + 16);
                    ahi[mi][3] = *(const uint32_t*)(ph + 8 * WROW_B + 16);
                    alo[mi][0] = *(const uint32_t*)(pl);
                    alo[mi][1] = *(const uint32_t*)(pl + 8 * WROW_B);
                    alo[mi][2] = *(const uint32_t*)(pl + 16);
                    alo[mi][3] = *(const uint32_t*)(pl + 8 * WROW_B + 16);
                }
                #pragma unroll
                for (int ni = 0; ni < 4; ni++) {
                    const int nr = ni * 8 + qr;
                    const char* ph = base + ST_XHI + nr * WROW_B + kb;
                    const char* pl = base + ST_XLO + nr * WROW_B + kb;
                    uint32_t bh[2], bl[2];
                    bh[0] = *(const uint32_t*)(ph);
                    bh[1] = *(const uint32_t*)(ph + 16);
                    bl[0] = *(const uint32_t*)(pl);
                    bl[1] = *(const uint32_t*)(pl + 16);
                    #pragma unroll
                    for (int mi = 0; mi < 2; mi++) {
                        mma_bf16(acc[mi][ni], ahi[mi], bh);
                        mma_bf16(acc[mi][ni], alo[mi], bh);
                        mma_bf16(acc[mi][ni], ahi[mi], bl);
                    }
                }
            }
        };

        ldg(0);
        sts(0);
        for (int c = 0; c < NCH; c++) {
            __syncthreads();
            if (c + 1 < NCH) ldg(c + 1);
            compute(c & 1);
            if (c + 1 < NCH) sts((c + 1) & 1);
        }

        /* epilogue */
        #pragma unroll
        for (int mi = 0; mi < 2; mi++) {
            const int mg = mbase + warp * 32 + mi * 16 + qr;
            const float b0 = bias[a * OUTF + mg];
            const float b8 = bias[a * OUTF + mg + 8];
            #pragma unroll
            for (int ni = 0; ni < 4; ni++) {
                const int n = ni * 8 + qc * 2;
                if (n < cntc) {
                    const int r = g_bucket[off + n0 + n];
                    out[(size_t)r * OUTF + mg]     = acc[mi][ni][0] + b0;
                    out[(size_t)r * OUTF + mg + 8] = acc[mi][ni][2] + b8;
                }
                if (n + 1 < cntc) {
                    const int r = g_bucket[off + n0 + n + 1];
                    out[(size_t)r * OUTF + mg]     = acc[mi][ni][1] + b0;
                    out[(size_t)r * OUTF + mg + 8] = acc[mi][ni][3] + b8;
                }
            }
        }
        __syncthreads();
    }
}

extern "C" void kernel_launch(void* const* d_in, const int* in_sizes, int n_in,
                              void* d_out, int out_size) {
    const int*   which = (const int*)d_in[0];
    const float* x     = (const float*)d_in[1];
    const float* w     = (const float*)d_in[2];
    const float* b     = (const float*)d_in[3];
    float* out = (float*)d_out;

    cudaFuncSetAttribute(agent_mma_kernel,
                         cudaFuncAttributeMaxDynamicSharedMemorySize, SM_TOT);

    bucket_kernel<<<1, 1024>>>(which);
    agent_mma_kernel<<<dim3(OUTF / MT, NAG, 2), 128, SM_TOT>>>(x, w, b, out);
}

// round 7
// speedup vs baseline: 1.7630x; 1.0304x over previous
#include <cuda_runtime.h>
#include <cuda_bf16.h>
#include <cstdint>

#define BATCH 2048
#define INF   512
#define OUTF  512
#define NAG   64

#define MT   128            /* block M (out features), 4 warps x 32 */
#define NT   32             /* block N (batch rows) */
#define TK   32             /* k chunk */
#define NCH  (INF / TK)     /* 16 */

/* smem per stage: Whi[128x32 bf16, row stride 80B] + Wlo + Xhi[32x32] + Xlo */
#define WROW_B   80
#define ST_WHI   0
#define ST_WLO   10240
#define ST_XHI   20480
#define ST_XLO   23040
#define ST_SIZE  25600
#define SM_TOT   (2 * ST_SIZE)   /* 51200 bytes */

__device__ int g_bucket[BATCH];
__device__ int g_offsets[NAG + 1];

__device__ __forceinline__ uint32_t smem_u32(const void* p) {
    uint32_t a;
    asm("{ .reg .u64 t; cvta.to.shared.u64 t, %1; cvt.u32.u64 %0, t; }" : "=r"(a) : "l"(p));
    return a;
}

#define LDSM_X4(r0, r1, r2, r3, addr) \
    asm volatile("ldmatrix.sync.aligned.m8n8.x4.shared.b16 {%0,%1,%2,%3}, [%4];" \
        : "=r"(r0), "=r"(r1), "=r"(r2), "=r"(r3) : "r"(addr))

/* split 2 floats into packed bf16 hi-word and residual lo-word (lo 16 bits = f0) */
__device__ __forceinline__ void split2(float f0, float f1, uint32_t& h, uint32_t& l) {
    asm("cvt.rn.bf16x2.f32 %0, %1, %2;" : "=r"(h) : "f"(f1), "f"(f0));
    float r0 = f0 - __uint_as_float(h << 16);
    float r1 = f1 - __uint_as_float(h & 0xFFFF0000u);
    asm("cvt.rn.bf16x2.f32 %0, %1, %2;" : "=r"(l) : "f"(r1), "f"(r0));
}

__device__ __forceinline__ void mma_bf16(float* c, const uint32_t* a, const uint32_t* b) {
    asm volatile(
        "mma.sync.aligned.m16n8k16.row.col.f32.bf16.bf16.f32 "
        "{%0,%1,%2,%3}, {%4,%5,%6,%7}, {%8,%9}, {%0,%1,%2,%3};"
        : "+f"(c[0]), "+f"(c[1]), "+f"(c[2]), "+f"(c[3])
        : "r"(a[0]), "r"(a[1]), "r"(a[2]), "r"(a[3]), "r"(b[0]), "r"(b[1]));
}

/* ---------------- kernel 1: counting sort by agent ---------------- */
__global__ __launch_bounds__(1024) void bucket_kernel(const int* __restrict__ which) {
    __shared__ int cnt[NAG];
    __shared__ int run[NAG];
    const int t = threadIdx.x;
    if (t < NAG) cnt[t] = 0;
    __syncthreads();
    for (int i = t; i < BATCH; i += blockDim.x) atomicAdd(&cnt[which[i]], 1);
    __syncthreads();
    if (t == 0) {
        int s = 0;
        for (int a = 0; a < NAG; a++) { run[a] = s; g_offsets[a] = s; s += cnt[a]; }
        g_offsets[NAG] = s;
    }
    __syncthreads();
    for (int i = t; i < BATCH; i += blockDim.x) {
        const int a = which[i];
        g_bucket[atomicAdd(&run[a], 1)] = i;
    }
}

/* ---------------- kernel 2: split-bf16 mma.sync GEMM, ldmatrix loads ---- */
__global__ __launch_bounds__(128) void agent_mma_kernel(
    const float* __restrict__ x, const float* __restrict__ w,
    const float* __restrict__ bias, float* __restrict__ out)
{
    extern __shared__ char sm[];
    const uint32_t sb = smem_u32(sm);
    const int a     = blockIdx.y;
    const int mbase = blockIdx.x * MT;
    const int off   = g_offsets[a];
    const int cnt   = g_offsets[a + 1] - off;

    const int t    = threadIdx.x;
    const int lane = t & 31;
    const int warp = t >> 5;
    const int qr   = lane >> 2;
    const int qc   = lane & 3;

    /* ldmatrix per-lane address bases (stage 0, kk 0) */
    const int aRow = ((lane >> 3) & 1) * 8;   /* A: mats 1,3 -> +8 rows */
    const int aK16 = ((lane >> 4) & 1) * 16;  /* A: mats 2,3 -> +8 k = +16B */
    const int bRow = ((lane >> 4) & 1) * 8;   /* B: mats 2,3 -> +8 n rows */
    const int bK16 = ((lane >> 3) & 1) * 16;  /* B: mats 1,3 -> +8 k */
    uint32_t awb[2], alb[2], bxb[2], blb[2];
    #pragma unroll
    for (int mi = 0; mi < 2; mi++) {
        const uint32_t ro = (uint32_t)(warp * 32 + mi * 16 + aRow + (lane & 7)) * WROW_B + aK16;
        awb[mi] = sb + ST_WHI + ro;
        alb[mi] = sb + ST_WLO + ro;
    }
    #pragma unroll
    for (int nb = 0; nb < 2; nb++) {
        const uint32_t ro = (uint32_t)(nb * 16 + bRow + (lane & 7)) * WROW_B + bK16;
        bxb[nb] = sb + ST_XHI + ro;
        blb[nb] = sb + ST_XLO + ro;
    }

    const float* Wrow = w + (size_t)a * OUTF * INF + (size_t)(mbase + t) * INF;
    const int xrow = t & 31, xq = t >> 5;

    float4 wpre[8], xpre[2];

    for (int n0 = blockIdx.z * NT; n0 < cnt; n0 += 2 * NT) {
        const int cntc = min(NT, cnt - n0);
        const int xg = (xrow < cntc) ? g_bucket[off + n0 + xrow] : g_bucket[off];
        const float* xp = x + (size_t)xg * INF + xq * 8;

        float acc[2][4][4];
        #pragma unroll
        for (int mi = 0; mi < 2; mi++)
            #pragma unroll
            for (int ni = 0; ni < 4; ni++)
                #pragma unroll
                for (int r = 0; r < 4; r++) acc[mi][ni][r] = 0.f;

        auto ldg = [&](int c) {
            const int k0 = c * TK;
            #pragma unroll
            for (int p = 0; p < 8; p++)
                wpre[p] = *(const float4*)(Wrow + k0 + p * 4);
            xpre[0] = *(const float4*)(xp + k0);
            xpre[1] = *(const float4*)(xp + k0 + 4);
        };

        auto sts = [&](int s) {
            char* base = sm + s * ST_SIZE;
            uint32_t hw[16], lw[16];
            #pragma unroll
            for (int p = 0; p < 8; p++) {
                split2(wpre[p].x, wpre[p].y, hw[2 * p],     lw[2 * p]);
                split2(wpre[p].z, wpre[p].w, hw[2 * p + 1], lw[2 * p + 1]);
            }
            char* dw = base + (uint32_t)t * WROW_B;
            #pragma unroll
            for (int q = 0; q < 4; q++) {
                *(uint4*)(dw + ST_WHI + q * 16) =
                    make_uint4(hw[4*q], hw[4*q+1], hw[4*q+2], hw[4*q+3]);
                *(uint4*)(dw + ST_WLO + q * 16) =
                    make_uint4(lw[4*q], lw[4*q+1], lw[4*q+2], lw[4*q+3]);
            }
            uint32_t hx[4], lx[4];
            split2(xpre[0].x, xpre[0].y, hx[0], lx[0]);
            split2(xpre[0].z, xpre[0].w, hx[1], lx[1]);
            split2(xpre[1].x, xpre[1].y, hx[2], lx[2]);
            split2(xpre[1].z, xpre[1].w, hx[3], lx[3]);
            char* dx = base + (uint32_t)xrow * WROW_B + xq * 16;
            *(uint4*)(dx + ST_XHI) = make_uint4(hx[0], hx[1], hx[2], hx[3]);
            *(uint4*)(dx + ST_XLO) = make_uint4(lx[0], lx[1], lx[2], lx[3]);
        };

        auto compute = [&](int s) {
            const uint32_t so = (uint32_t)s * ST_SIZE;
            #pragma unroll
            for (int kk = 0; kk < 2; kk++) {
                const uint32_t ko = so + kk * 32;
                uint32_t ahi[2][4], alo[2][4];
                #pragma unroll
                for (int mi = 0; mi < 2; mi++) {
                    LDSM_X4(ahi[mi][0], ahi[mi][1], ahi[mi][2], ahi[mi][3], awb[mi] + ko);
                    LDSM_X4(alo[mi][0], alo[mi][1], alo[mi][2], alo[mi][3], alb[mi] + ko);
                }
                #pragma unroll
                for (int nb = 0; nb < 2; nb++) {
                    uint32_t bh4[4], bl4[4];
                    LDSM_X4(bh4[0], bh4[1], bh4[2], bh4[3], bxb[nb] + ko);
                    LDSM_X4(bl4[0], bl4[1], bl4[2], bl4[3], blb[nb] + ko);
                    #pragma unroll
                    for (int half = 0; half < 2; half++) {
                        const int ni = nb * 2 + half;
                        uint32_t bh[2] = {bh4[2 * half], bh4[2 * half + 1]};
                        uint32_t bl[2] = {bl4[2 * half], bl4[2 * half + 1]};
                        #pragma unroll
                        for (int mi = 0; mi < 2; mi++) {
                            mma_bf16(acc[mi][ni], ahi[mi], bh);
                            mma_bf16(acc[mi][ni], alo[mi], bh);
                            mma_bf16(acc[mi][ni], ahi[mi], bl);
                        }
                    }
                }
            }
        };

        ldg(0);
        sts(0);
        for (int c = 0; c < NCH; c++) {
            __syncthreads();
            if (c + 1 < NCH) ldg(c + 1);
            compute(c & 1);
            if (c + 1 < NCH) sts((c + 1) & 1);
        }

        /* epilogue */
        #pragma unroll
        for (int mi = 0; mi < 2; mi++) {
            const int mg = mbase + warp * 32 + mi * 16 + qr;
            const float b0 = bias[a * OUTF + mg];
            const float b8 = bias[a * OUTF + mg + 8];
            #pragma unroll
            for (int ni = 0; ni < 4; ni++) {
                const int n = ni * 8 + qc * 2;
                if (n < cntc) {
                    const int r = g_bucket[off + n0 + n];
                    out[(size_t)r * OUTF + mg]     = acc[mi][ni][0] + b0;
                    out[(size_t)r * OUTF + mg + 8] = acc[mi][ni][2] + b8;
                }
                if (n + 1 < cntc) {
                    const int r = g_bucket[off + n0 + n + 1];
                    out[(size_t)r * OUTF + mg]     = acc[mi][ni][1] + b0;
                    out[(size_t)r * OUTF + mg + 8] = acc[mi][ni][3] + b8;
                }
            }
        }
        __syncthreads();
    }
}

extern "C" void kernel_launch(void* const* d_in, const int* in_sizes, int n_in,
                              void* d_out, int out_size) {
    const int*   which = (const int*)d_in[0];
    const float* x     = (const float*)d_in[1];
    const float* w     = (const float*)d_in[2];
    const float* b     = (const float*)d_in[3];
    float* out = (float*)d_out;

    cudaFuncSetAttribute(agent_mma_kernel,
                         cudaFuncAttributeMaxDynamicSharedMemorySize, SM_TOT);

    bucket_kernel<<<1, 1024>>>(which);
    agent_mma_kernel<<<dim3(OUTF / MT, NAG, 2), 128, SM_TOT>>>(x, w, b, out);
}

// round 8
// speedup vs baseline: 2.7106x; 1.5375x over previous
#include <cuda_runtime.h>
#include <cuda_bf16.h>
#include <cstdint>

#define BATCH 2048
#define INF   512
#define OUTF  512
#define NAG   64

#define MT   128            /* block M (out features), 4 warps x 32 */
#define NT   32             /* block N (batch rows) */
#define TK   32             /* k chunk */
#define NCH  (INF / TK)     /* 16 */

/* smem per stage: Whi[128x32 bf16, row stride 80B] + Wlo + Xhi[32x32] + Xlo */
#define WROW_B   80
#define ST_WHI   0
#define ST_WLO   10240
#define ST_XHI   20480
#define ST_XLO   23040
#define ST_SIZE  25600
#define SM_TOT   (2 * ST_SIZE)   /* 51200 bytes */

__device__ int g_bucket[BATCH];
__device__ int g_offsets[NAG + 1];

__device__ __forceinline__ uint32_t smem_u32(const void* p) {
    uint32_t a;
    asm("{ .reg .u64 t; cvta.to.shared.u64 t, %1; cvt.u32.u64 %0, t; }" : "=r"(a) : "l"(p));
    return a;
}

#define LDSM_X4(r0, r1, r2, r3, addr) \
    asm volatile("ldmatrix.sync.aligned.m8n8.x4.shared.b16 {%0,%1,%2,%3}, [%4];" \
        : "=r"(r0), "=r"(r1), "=r"(r2), "=r"(r3) : "r"(addr))

/* split 2 floats into packed bf16 hi-word and residual lo-word (lo 16 bits = f0) */
__device__ __forceinline__ void split2(float f0, float f1, uint32_t& h, uint32_t& l) {
    asm("cvt.rn.bf16x2.f32 %0, %1, %2;" : "=r"(h) : "f"(f1), "f"(f0));
    float r0 = f0 - __uint_as_float(h << 16);
    float r1 = f1 - __uint_as_float(h & 0xFFFF0000u);
    asm("cvt.rn.bf16x2.f32 %0, %1, %2;" : "=r"(l) : "f"(r1), "f"(r0));
}

__device__ __forceinline__ void mma_bf16(float* c, const uint32_t* a, const uint32_t* b) {
    asm volatile(
        "mma.sync.aligned.m16n8k16.row.col.f32.bf16.bf16.f32 "
        "{%0,%1,%2,%3}, {%4,%5,%6,%7}, {%8,%9}, {%0,%1,%2,%3};"
        : "+f"(c[0]), "+f"(c[1]), "+f"(c[2]), "+f"(c[3])
        : "r"(a[0]), "r"(a[1]), "r"(a[2]), "r"(a[3]), "r"(b[0]), "r"(b[1]));
}

/* ---------------- kernel 1: counting sort by agent ---------------- */
__global__ __launch_bounds__(1024) void bucket_kernel(const int* __restrict__ which) {
    __shared__ int cnt[NAG];
    __shared__ int run[NAG];
    const int t = threadIdx.x;
    if (t < NAG) cnt[t] = 0;
    __syncthreads();
    for (int i = t; i < BATCH; i += blockDim.x) atomicAdd(&cnt[which[i]], 1);
    __syncthreads();
    if (t == 0) {
        int s = 0;
        for (int a = 0; a < NAG; a++) { run[a] = s; g_offsets[a] = s; s += cnt[a]; }
        g_offsets[NAG] = s;
    }
    __syncthreads();
    for (int i = t; i < BATCH; i += blockDim.x) {
        const int a = which[i];
        g_bucket[atomicAdd(&run[a], 1)] = i;
    }
}

/* ---------------- kernel 2: split-bf16 mma.sync GEMM ----------------
   W LDG coalesced: warp lane -> (row = lane>>3, col4 = lane&7); each LDG.128
   covers 4 full 128B lines (was 32 lines/instr with row-per-thread).
*/
__global__ __launch_bounds__(128) void agent_mma_kernel(
    const float* __restrict__ x, const float* __restrict__ w,
    const float* __restrict__ bias, float* __restrict__ out)
{
    extern __shared__ char sm[];
    const uint32_t sb = smem_u32(sm);
    const int a     = blockIdx.y;
    const int mbase = blockIdx.x * MT;
    const int off   = g_offsets[a];
    const int cnt   = g_offsets[a + 1] - off;

    const int t    = threadIdx.x;
    const int lane = t & 31;
    const int warp = t >> 5;
    const int qr   = lane >> 2;
    const int qc   = lane & 3;

    /* ldmatrix per-lane address bases */
    const int aRow = ((lane >> 3) & 1) * 8;
    const int aK16 = ((lane >> 4) & 1) * 16;
    const int bRow = ((lane >> 4) & 1) * 8;
    const int bK16 = ((lane >> 3) & 1) * 16;
    uint32_t awb[2], alb[2], bxb[2], blb[2];
    #pragma unroll
    for (int mi = 0; mi < 2; mi++) {
        const uint32_t ro = (uint32_t)(warp * 32 + mi * 16 + aRow + (lane & 7)) * WROW_B + aK16;
        awb[mi] = sb + ST_WHI + ro;
        alb[mi] = sb + ST_WLO + ro;
    }
    #pragma unroll
    for (int nb = 0; nb < 2; nb++) {
        const uint32_t ro = (uint32_t)(nb * 16 + bRow + (lane & 7)) * WROW_B + bK16;
        bxb[nb] = sb + ST_XHI + ro;
        blb[nb] = sb + ST_XLO + ro;
    }

    /* coalesced W load mapping: 4 rows per warp-pass, 8 passes per chunk */
    const int wlr = lane >> 3;        /* row within 4-row group */
    const int wlc = lane & 7;         /* float4 column 0..7     */
    const float* Wbase = w + (size_t)a * OUTF * INF
                       + (size_t)(mbase + warp * 32 + wlr) * INF + wlc * 4;
    const uint32_t wsrow = (uint32_t)(warp * 32 + wlr);

    const int xrow = t & 31, xq = t >> 5;

    float4 wpre[8], xpre[2];

    for (int n0 = blockIdx.z * NT; n0 < cnt; n0 += 2 * NT) {
        const int cntc = min(NT, cnt - n0);
        const int xg = (xrow < cntc) ? g_bucket[off + n0 + xrow] : g_bucket[off];
        const float* xp = x + (size_t)xg * INF + xq * 8;

        float acc[2][4][4];
        #pragma unroll
        for (int mi = 0; mi < 2; mi++)
            #pragma unroll
            for (int ni = 0; ni < 4; ni++)
                #pragma unroll
                for (int r = 0; r < 4; r++) acc[mi][ni][r] = 0.f;

        auto ldg = [&](int c) {
            const int k0 = c * TK;
            #pragma unroll
            for (int ro = 0; ro < 8; ro++)
                wpre[ro] = *(const float4*)(Wbase + (size_t)ro * 4 * INF + k0);
            xpre[0] = *(const float4*)(xp + k0);
            xpre[1] = *(const float4*)(xp + k0 + 4);
        };

        auto sts = [&](int s) {
            char* base = sm + s * ST_SIZE;
            char* dw = base + wsrow * WROW_B + wlc * 8;
            #pragma unroll
            for (int ro = 0; ro < 8; ro++) {
                uint32_t h0, l0, h1, l1;
                split2(wpre[ro].x, wpre[ro].y, h0, l0);
                split2(wpre[ro].z, wpre[ro].w, h1, l1);
                const uint32_t roff = (uint32_t)ro * 4 * WROW_B;
                *(uint2*)(dw + ST_WHI + roff) = make_uint2(h0, h1);
                *(uint2*)(dw + ST_WLO + roff) = make_uint2(l0, l1);
            }
            uint32_t hx[4], lx[4];
            split2(xpre[0].x, xpre[0].y, hx[0], lx[0]);
            split2(xpre[0].z, xpre[0].w, hx[1], lx[1]);
            split2(xpre[1].x, xpre[1].y, hx[2], lx[2]);
            split2(xpre[1].z, xpre[1].w, hx[3], lx[3]);
            char* dx = base + (uint32_t)xrow * WROW_B + xq * 16;
            *(uint4*)(dx + ST_XHI) = make_uint4(hx[0], hx[1], hx[2], hx[3]);
            *(uint4*)(dx + ST_XLO) = make_uint4(lx[0], lx[1], lx[2], lx[3]);
        };

        auto compute = [&](int s) {
            const uint32_t so = (uint32_t)s * ST_SIZE;
            #pragma unroll
            for (int kk = 0; kk < 2; kk++) {
                const uint32_t ko = so + kk * 32;
                uint32_t ahi[2][4], alo[2][4];
                #pragma unroll
                for (int mi = 0; mi < 2; mi++) {
                    LDSM_X4(ahi[mi][0], ahi[mi][1], ahi[mi][2], ahi[mi][3], awb[mi] + ko);
                    LDSM_X4(alo[mi][0], alo[mi][1], alo[mi][2], alo[mi][3], alb[mi] + ko);
                }
                #pragma unroll
                for (int nb = 0; nb < 2; nb++) {
                    uint32_t bh4[4], bl4[4];
                    LDSM_X4(bh4[0], bh4[1], bh4[2], bh4[3], bxb[nb] + ko);
                    LDSM_X4(bl4[0], bl4[1], bl4[2], bl4[3], blb[nb] + ko);
                    #pragma unroll
                    for (int half = 0; half < 2; half++) {
                        const int ni = nb * 2 + half;
                        uint32_t bh[2] = {bh4[2 * half], bh4[2 * half + 1]};
                        uint32_t bl[2] = {bl4[2 * half], bl4[2 * half + 1]};
                        #pragma unroll
                        for (int mi = 0; mi < 2; mi++) {
                            mma_bf16(acc[mi][ni], ahi[mi], bh);
                            mma_bf16(acc[mi][ni], alo[mi], bh);
                            mma_bf16(acc[mi][ni], ahi[mi], bl);
                        }
                    }
                }
            }
        };

        ldg(0);
        sts(0);
        for (int c = 0; c < NCH; c++) {
            __syncthreads();
            if (c + 1 < NCH) ldg(c + 1);
            compute(c & 1);
            if (c + 1 < NCH) sts((c + 1) & 1);
        }

        /* epilogue */
        #pragma unroll
        for (int mi = 0; mi < 2; mi++) {
            const int mg = mbase + warp * 32 + mi * 16 + qr;
            const float b0 = bias[a * OUTF + mg];
            const float b8 = bias[a * OUTF + mg + 8];
            #pragma unroll
            for (int ni = 0; ni < 4; ni++) {
                const int n = ni * 8 + qc * 2;
                if (n < cntc) {
                    const int r = g_bucket[off + n0 + n];
                    out[(size_t)r * OUTF + mg]     = acc[mi][ni][0] + b0;
                    out[(size_t)r * OUTF + mg + 8] = acc[mi][ni][2] + b8;
                }
                if (n + 1 < cntc) {
                    const int r = g_bucket[off + n0 + n + 1];
                    out[(size_t)r * OUTF + mg]     = acc[mi][ni][1] + b0;
                    out[(size_t)r * OUTF + mg + 8] = acc[mi][ni][3] + b8;
                }
            }
        }
        __syncthreads();
    }
}

extern "C" void kernel_launch(void* const* d_in, const int* in_sizes, int n_in,
                              void* d_out, int out_size) {
    const int*   which = (const int*)d_in[0];
    const float* x     = (const float*)d_in[1];
    const float* w     = (const float*)d_in[2];
    const float* b     = (const float*)d_in[3];
    float* out = (float*)d_out;

    cudaFuncSetAttribute(agent_mma_kernel,
                         cudaFuncAttributeMaxDynamicSharedMemorySize, SM_TOT);

    bucket_kernel<<<1, 1024>>>(which);
    agent_mma_kernel<<<dim3(OUTF / MT, NAG, 2), 128, SM_TOT>>>(x, w, b, out);
}

// round 9
// speedup vs baseline: 3.0359x; 1.1200x over previous
#include <cuda_runtime.h>
#include <cuda_bf16.h>
#include <cstdint>

#define BATCH 2048
#define INF   512
#define OUTF  512
#define NAG   64

#define MT   128            /* block M (out features), 4 warps x 32 */
#define NT   32             /* block N (batch rows) */
#define TK   32             /* k chunk */
#define NCH  (INF / TK)     /* 16 */

/* smem per stage: Whi[128x32 bf16, row stride 80B] + Wlo + Xhi[32x32] + Xlo */
#define WROW_B   80
#define ST_WHI   0
#define ST_WLO   10240
#define ST_XHI   20480
#define ST_XLO   23040
#define ST_SIZE  25600
#define SM_TOT   (2 * ST_SIZE)   /* 51200 bytes */

__device__ int g_bucket[BATCH];
__device__ int g_offsets[NAG + 1];
/* X pre-converted: per (chunk, row): 32 u32 = [q0: 4 hi, 4 lo][q1: ...] 128B */
__device__ uint32_t g_xs[NCH][BATCH][32];

__device__ __forceinline__ uint32_t smem_u32(const void* p) {
    uint32_t a;
    asm("{ .reg .u64 t; cvta.to.shared.u64 t, %1; cvt.u32.u64 %0, t; }" : "=r"(a) : "l"(p));
    return a;
}

#define LDSM_X4(r0, r1, r2, r3, addr) \
    asm volatile("ldmatrix.sync.aligned.m8n8.x4.shared.b16 {%0,%1,%2,%3}, [%4];" \
        : "=r"(r0), "=r"(r1), "=r"(r2), "=r"(r3) : "r"(addr))

/* split 2 floats into packed bf16 hi-word and residual lo-word (lo 16 bits = f0) */
__device__ __forceinline__ void split2(float f0, float f1, uint32_t& h, uint32_t& l) {
    asm("cvt.rn.bf16x2.f32 %0, %1, %2;" : "=r"(h) : "f"(f1), "f"(f0));
    float r0 = f0 - __uint_as_float(h << 16);
    float r1 = f1 - __uint_as_float(h & 0xFFFF0000u);
    asm("cvt.rn.bf16x2.f32 %0, %1, %2;" : "=r"(l) : "f"(r1), "f"(r0));
}

__device__ __forceinline__ void mma_bf16(float* c, const uint32_t* a, const uint32_t* b) {
    asm volatile(
        "mma.sync.aligned.m16n8k16.row.col.f32.bf16.bf16.f32 "
        "{%0,%1,%2,%3}, {%4,%5,%6,%7}, {%8,%9}, {%0,%1,%2,%3};"
        : "+f"(c[0]), "+f"(c[1]), "+f"(c[2]), "+f"(c[3])
        : "r"(a[0]), "r"(a[1]), "r"(a[2]), "r"(a[3]), "r"(b[0]), "r"(b[1]));
}

/* ------- kernel 1: block 0 = counting sort; blocks 1.. = X convert ------- */
__global__ __launch_bounds__(256) void prep_kernel(
    const int* __restrict__ which, const float* __restrict__ x)
{
    const int t = threadIdx.x;
    if (blockIdx.x == 0) {
        __shared__ int cnt[NAG];
        __shared__ int run[NAG];
        if (t < NAG) cnt[t] = 0;
        __syncthreads();
        for (int i = t; i < BATCH; i += 256) atomicAdd(&cnt[which[i]], 1);
        __syncthreads();
        if (t == 0) {
            int s = 0;
            for (int a = 0; a < NAG; a++) { run[a] = s; g_offsets[a] = s; s += cnt[a]; }
            g_offsets[NAG] = s;
        }
        __syncthreads();
        for (int i = t; i < BATCH; i += 256) {
            const int a = which[i];
            g_bucket[atomicAdd(&run[a], 1)] = i;
        }
        return;
    }
    /* convert: 16 rows per block (8 warps x 2 rows, half-warp per row) */
    const int warp = t >> 5, lane = t & 31;
    const int row = (blockIdx.x - 1) * 16 + warp * 2 + (lane >> 4);
    if (row >= BATCH) return;
    const int p = lane & 15;                 /* k-pair within chunk */
    const float2* xr = (const float2*)(x + (size_t)row * INF) + p;
    const int q = p >> 2, w = p & 3;
    #pragma unroll
    for (int c = 0; c < NCH; c++) {
        const float2 v = xr[c * 16];
        uint32_t h, l;
        split2(v.x, v.y, h, l);
        uint32_t* dst = g_xs[c][row];
        dst[q * 8 + w]     = h;
        dst[q * 8 + 4 + w] = l;
    }
}

/* ---------------- kernel 2: split-bf16 mma.sync GEMM ---------------- */
__global__ __launch_bounds__(128) void agent_mma_kernel(
    const float* __restrict__ x, const float* __restrict__ w,
    const float* __restrict__ bias, float* __restrict__ out)
{
    extern __shared__ char sm[];
    const uint32_t sb = smem_u32(sm);
    const int a     = blockIdx.y;
    const int mbase = blockIdx.x * MT;
    const int off   = g_offsets[a];
    const int cnt   = g_offsets[a + 1] - off;

    const int t    = threadIdx.x;
    const int lane = t & 31;
    const int warp = t >> 5;
    const int qr   = lane >> 2;
    const int qc   = lane & 3;

    /* ldmatrix per-lane address bases */
    const int aRow = ((lane >> 3) & 1) * 8;
    const int aK16 = ((lane >> 4) & 1) * 16;
    const int bRow = ((lane >> 4) & 1) * 8;
    const int bK16 = ((lane >> 3) & 1) * 16;
    uint32_t awb[2], alb[2], bxb[2], blb[2];
    #pragma unroll
    for (int mi = 0; mi < 2; mi++) {
        const uint32_t ro = (uint32_t)(warp * 32 + mi * 16 + aRow + (lane & 7)) * WROW_B + aK16;
        awb[mi] = sb + ST_WHI + ro;
        alb[mi] = sb + ST_WLO + ro;
    }
    #pragma unroll
    for (int nb = 0; nb < 2; nb++) {
        const uint32_t ro = (uint32_t)(nb * 16 + bRow + (lane & 7)) * WROW_B + bK16;
        bxb[nb] = sb + ST_XHI + ro;
        blb[nb] = sb + ST_XLO + ro;
    }

    /* coalesced W load mapping: 4 rows per warp-pass, 8 passes per chunk */
    const int wlr = lane >> 3;
    const int wlc = lane & 7;
    const float* Wbase = w + (size_t)a * OUTF * INF
                       + (size_t)(mbase + warp * 32 + wlr) * INF + wlc * 4;
    const uint32_t wsrow = (uint32_t)(warp * 32 + wlr);

    /* X load mapping: slot = t>>2 (0..31), q = t&3 */
    const int xslot = t >> 2, xq4 = t & 3;

    float4 wpre[8];
    uint4 xh4, xl4;

    for (int n0 = blockIdx.z * NT; n0 < cnt; n0 += 2 * NT) {
        const int cntc = min(NT, cnt - n0);
        int sg = off + n0 + xslot;
        if (sg > BATCH - 1) sg = BATCH - 1;
        const int xrowg = g_bucket[sg];

        float acc[2][4][4];
        #pragma unroll
        for (int mi = 0; mi < 2; mi++)
            #pragma unroll
            for (int ni = 0; ni < 4; ni++)
                #pragma unroll
                for (int r = 0; r < 4; r++) acc[mi][ni][r] = 0.f;

        auto ldg = [&](int c) {
            const int k0 = c * TK;
            #pragma unroll
            for (int ro = 0; ro < 8; ro++)
                wpre[ro] = *(const float4*)(Wbase + (size_t)ro * 4 * INF + k0);
            xh4 = *(const uint4*)&g_xs[c][xrowg][xq4 * 8];
            xl4 = *(const uint4*)&g_xs[c][xrowg][xq4 * 8 + 4];
        };

        auto sts = [&](int s) {
            char* base = sm + s * ST_SIZE;
            char* dw = base + wsrow * WROW_B + wlc * 8;
            #pragma unroll
            for (int ro = 0; ro < 8; ro++) {
                uint32_t h0, l0, h1, l1;
                split2(wpre[ro].x, wpre[ro].y, h0, l0);
                split2(wpre[ro].z, wpre[ro].w, h1, l1);
                const uint32_t roff = (uint32_t)ro * 4 * WROW_B;
                *(uint2*)(dw + ST_WHI + roff) = make_uint2(h0, h1);
                *(uint2*)(dw + ST_WLO + roff) = make_uint2(l0, l1);
            }
            char* dx = base + (uint32_t)xslot * WROW_B + xq4 * 16;
            *(uint4*)(dx + ST_XHI) = xh4;
            *(uint4*)(dx + ST_XLO) = xl4;
        };

        auto compute = [&](int s) {
            const uint32_t so = (uint32_t)s * ST_SIZE;
            #pragma unroll
            for (int kk = 0; kk < 2; kk++) {
                const uint32_t ko = so + kk * 32;
                uint32_t ahi[2][4], alo[2][4];
                #pragma unroll
                for (int mi = 0; mi < 2; mi++) {
                    LDSM_X4(ahi[mi][0], ahi[mi][1], ahi[mi][2], ahi[mi][3], awb[mi] + ko);
                    LDSM_X4(alo[mi][0], alo[mi][1], alo[mi][2], alo[mi][3], alb[mi] + ko);
                }
                #pragma unroll
                for (int nb = 0; nb < 2; nb++) {
                    uint32_t bh4[4], bl4[4];
                    LDSM_X4(bh4[0], bh4[1], bh4[2], bh4[3], bxb[nb] + ko);
                    LDSM_X4(bl4[0], bl4[1], bl4[2], bl4[3], blb[nb] + ko);
                    #pragma unroll
                    for (int half = 0; half < 2; half++) {
                        const int ni = nb * 2 + half;
                        uint32_t bh[2] = {bh4[2 * half], bh4[2 * half + 1]};
                        uint32_t bl[2] = {bl4[2 * half], bl4[2 * half + 1]};
                        #pragma unroll
                        for (int mi = 0; mi < 2; mi++) {
                            mma_bf16(acc[mi][ni], ahi[mi], bh);
                            mma_bf16(acc[mi][ni], alo[mi], bh);
                            mma_bf16(acc[mi][ni], ahi[mi], bl);
                        }
                    }
                }
            }
        };

        ldg(0);
        sts(0);
        for (int c = 0; c < NCH; c++) {
            __syncthreads();
            if (c + 1 < NCH) ldg(c + 1);
            compute(c & 1);
            if (c + 1 < NCH) sts((c + 1) & 1);
        }

        /* epilogue */
        #pragma unroll
        for (int mi = 0; mi < 2; mi++) {
            const int mg = mbase + warp * 32 + mi * 16 + qr;
            const float b0 = bias[a * OUTF + mg];
            const float b8 = bias[a * OUTF + mg + 8];
            #pragma unroll
            for (int ni = 0; ni < 4; ni++) {
                const int n = ni * 8 + qc * 2;
                if (n < cntc) {
                    const int r = g_bucket[off + n0 + n];
                    out[(size_t)r * OUTF + mg]     = acc[mi][ni][0] + b0;
                    out[(size_t)r * OUTF + mg + 8] = acc[mi][ni][2] + b8;
                }
                if (n + 1 < cntc) {
                    const int r = g_bucket[off + n0 + n + 1];
                    out[(size_t)r * OUTF + mg]     = acc[mi][ni][1] + b0;
                    out[(size_t)r * OUTF + mg + 8] = acc[mi][ni][3] + b8;
                }
            }
        }
        __syncthreads();
    }
}

extern "C" void kernel_launch(void* const* d_in, const int* in_sizes, int n_in,
                              void* d_out, int out_size) {
    const int*   which = (const int*)d_in[0];
    const float* x     = (const float*)d_in[1];
    const float* w     = (const float*)d_in[2];
    const float* b     = (const float*)d_in[3];
    float* out = (float*)d_out;

    cudaFuncSetAttribute(agent_mma_kernel,
                         cudaFuncAttributeMaxDynamicSharedMemorySize, SM_TOT);

    prep_kernel<<<1 + (BATCH + 15) / 16, 256>>>(which, x);
    agent_mma_kernel<<<dim3(OUTF / MT, NAG, 2), 128, SM_TOT>>>(x, w, b, out);
}